// round 15
// baseline (speedup 1.0000x reference)
#include <cuda_runtime.h>
#include <cuda_fp16.h>
#include <cstdint>
#include <math.h>

// Problem constants
#define B_   128
#define T_   20
#define D_   512
#define H_   512
#define V_   32000
#define NCLS 1000
#define TOPK 5
#define BN_EPS 1e-5f

// ---------------- scratch (device globals; no allocation allowed) ----------
__device__ float d_cls[B_ * D_];
__device__ float d_proj[B_ * D_];
__device__ float d_X[B_ * T_ * D_];
__device__ float d_GI[B_ * T_ * 3 * H_];
__device__ float d_h0[B_ * H_];
__device__ float d_h1[B_ * H_];
__device__ __half d_h16h[2 * B_ * H_];
__device__ __half d_h16l[2 * B_ * H_];
__device__ unsigned d_bar[T_];
__device__ float d_feats[B_ * T_ * 2 * H_];
__device__ float d_u[B_ * T_ * H_];
__device__ float d_attn_WT[H_ * H_];
__device__ __half d_Afh[B_ * T_ * 2 * H_];
__device__ __half d_Bvh[(size_t)V_ * 2 * H_];

// ---------------- helpers ---------------------------------------------------
__device__ __forceinline__ void mma_f16(float* c, const unsigned* a, const unsigned* b) {
    asm volatile(
        "mma.sync.aligned.m16n8k16.row.col.f32.f16.f16.f32 "
        "{%0,%1,%2,%3}, {%4,%5,%6,%7}, {%8,%9}, {%0,%1,%2,%3};"
        : "+f"(c[0]), "+f"(c[1]), "+f"(c[2]), "+f"(c[3])
        : "r"(a[0]), "r"(a[1]), "r"(a[2]), "r"(a[3]), "r"(b[0]), "r"(b[1]));
}
__device__ __forceinline__ void ldsm_x4(unsigned* r, uint32_t addr) {
    asm volatile(
        "ldmatrix.sync.aligned.m8n8.x4.shared.b16 {%0,%1,%2,%3}, [%4];"
        : "=r"(r[0]), "=r"(r[1]), "=r"(r[2]), "=r"(r[3]) : "r"(addr));
}
__device__ __forceinline__ float sigmoidf_(float x) { return 1.0f / (1.0f + expf(-x)); }

__device__ __forceinline__ void cp16(uint32_t dst, const void* src) {
    asm volatile("cp.async.cg.shared.global [%0], [%1], 16;" :: "r"(dst), "l"(src));
}

// split f32 -> (hi, lo) halves and store 4-wide at smem offset (half units)
__device__ __forceinline__ void split_store4(
    __half* hiP, __half* loP, int off, float4 v)
{
    __half h0 = __float2half_rn(v.x), h1 = __float2half_rn(v.y);
    __half h2 = __float2half_rn(v.z), h3 = __float2half_rn(v.w);
    __half l0 = __float2half_rn(v.x - __half2float(h0));
    __half l1 = __float2half_rn(v.y - __half2float(h1));
    __half l2 = __float2half_rn(v.z - __half2float(h2));
    __half l3 = __float2half_rn(v.w - __half2float(h3));
    __half2 a0 = __halves2half2(h0, h1), a1 = __halves2half2(h2, h3);
    __half2 b0 = __halves2half2(l0, l1), b1 = __halves2half2(l2, l3);
    uint2 hv, lv;
    hv.x = *(unsigned*)&a0; hv.y = *(unsigned*)&a1;
    lv.x = *(unsigned*)&b0; lv.y = *(unsigned*)&b1;
    *(uint2*)(hiP + off) = hv;
    *(uint2*)(loP + off) = lv;
}

// ---------------- f32 -> f16 conversion (grid-stride, 8B stores) -------------
__global__ void __launch_bounds__(256) f2h_kernel(
    const float* __restrict__ src, __half* __restrict__ dst, int n4)
{
    const int stride = gridDim.x * 256;
    for (int i = blockIdx.x * 256 + threadIdx.x; i < n4; i += stride) {
        float4 v = ((const float4*)src)[i];
        __half2 lo = __floats2half2_rn(v.x, v.y);
        __half2 hi = __floats2half2_rn(v.z, v.w);
        uint2 o;
        o.x = *(unsigned*)&lo;
        o.y = *(unsigned*)&hi;
        ((uint2*)dst)[i] = o;
    }
}

// ---------------- vocab GEMM: 128x256 tile, 512 thr, 32x64 warp tile ---------
// C = A @ B^T + bias.  A (M,K) half, B (N,K) half, C (M,N) f32.
// grid = (M/128, N/256), M fastest.  3-stage cp.async; dyn smem 147456 B
// (3 stages x (A 16K + B 32K)).  1 CTA/SM (16 warps), acc 64 regs/thread.
__global__ void __launch_bounds__(512, 1) vgemm256_kernel(
    const __half* __restrict__ A, const __half* __restrict__ Bm,
    const float* __restrict__ bias, float* __restrict__ C,
    int K, int ldc)
{
    extern __shared__ char hs[];

    const int bm = blockIdx.x * 128;
    const int bn = blockIdx.y * 256;
    const int tid = threadIdx.x;
    const int warp = tid >> 5, lane = tid & 31;
    const int wm = (warp >> 2) * 32;       // 4 warp rows  (covers 128)
    const int wn = (warp & 3) * 64;        // 4 warp cols  (covers 256)
    const int g = lane >> 2, tg = lane & 3;

    // cp.async mapping
    // A: 128 rows x 8 chunks = 1024 -> 4 thr/row, 2 chunks each
    const int lrA  = tid >> 2;
    const int lcA  = (tid & 3) * 2;
    const int rsA  = lrA & 7;
    // B: 256 rows x 8 chunks = 2048 -> 2 thr/row, 4 chunks each
    const int lrB  = tid >> 1;
    const int lcB  = (tid & 1) * 4;
    const int rsB  = lrB & 7;
    const __half* gA = A + (size_t)(bm + lrA) * K + lcA * 8;
    const __half* gB = Bm + (size_t)(bn + lrB) * K + lcB * 8;
    const uint32_t sbase = (uint32_t)__cvta_generic_to_shared(hs);
    const uint32_t sA = sbase + lrA * 128;
    const uint32_t sB = sbase + 16384 + lrB * 128;

    // ldmatrix lane roles
    const int arow = ((lane >> 3) & 1) * 8 + (lane & 7);
    const int ako  = lane >> 4;
    const int axor = lane & 7;
    const int brow = ((lane >> 4) << 3) + (lane & 7);
    const int bko  = (lane >> 3) & 1;
    const int bxor = lane & 7;
    uint32_t aoff[2], boff[4];
#pragma unroll
    for (int mi = 0; mi < 2; mi++) aoff[mi] = (uint32_t)((wm + mi * 16 + arow) * 128);
#pragma unroll
    for (int nj = 0; nj < 4; nj++) boff[nj] = (uint32_t)(16384 + (wn + nj * 16 + brow) * 128);

#define HISSUE(st_, k0_) do {                                        \
        uint32_t o_ = (uint32_t)(st_) * 49152u;                      \
        _Pragma("unroll")                                            \
        for (int c_ = 0; c_ < 2; c_++) {                             \
            uint32_t sw_ = (uint32_t)(((lcA + c_) ^ rsA) << 4);      \
            cp16(sA + o_ + sw_, gA + (k0_) + c_ * 8);                \
        }                                                            \
        _Pragma("unroll")                                            \
        for (int c_ = 0; c_ < 4; c_++) {                             \
            uint32_t sw_ = (uint32_t)(((lcB + c_) ^ rsB) << 4);      \
            cp16(sB + o_ + sw_, gB + (k0_) + c_ * 8);                \
        }                                                            \
        asm volatile("cp.async.commit_group;");                      \
    } while (0)

    const int niter = K >> 6;
    HISSUE(0, 0);
    HISSUE(1, 64);

    float acc[2][8][4];
#pragma unroll
    for (int i = 0; i < 2; i++)
#pragma unroll
        for (int j = 0; j < 8; j++)
#pragma unroll
            for (int k = 0; k < 4; k++) acc[i][j][k] = 0.0f;

    for (int it = 0; it < niter; it++) {
        if (it + 1 < niter) asm volatile("cp.async.wait_group 1;");
        else                asm volatile("cp.async.wait_group 0;");
        __syncthreads();
        if (it + 2 < niter) HISSUE((it + 2) % 3, (it + 2) * 64);

        const uint32_t st = sbase + (uint32_t)(it % 3) * 49152u;
#pragma unroll
        for (int kk = 0; kk < 64; kk += 16) {
            const int ch0 = kk >> 3;
            unsigned a[2][4], bq[4][4];
#pragma unroll
            for (int mi = 0; mi < 2; mi++)
                ldsm_x4(a[mi], st + aoff[mi] + (uint32_t)((((ch0 + ako) ^ axor)) << 4));
#pragma unroll
            for (int nj = 0; nj < 4; nj++)
                ldsm_x4(bq[nj], st + boff[nj] + (uint32_t)((((ch0 + bko) ^ bxor)) << 4));
#pragma unroll
            for (int mi = 0; mi < 2; mi++)
#pragma unroll
                for (int nj = 0; nj < 4; nj++) {
                    mma_f16(acc[mi][2 * nj],     a[mi], &bq[nj][0]);
                    mma_f16(acc[mi][2 * nj + 1], a[mi], &bq[nj][2]);
                }
        }
        __syncthreads();
    }
#undef HISSUE

#pragma unroll
    for (int mi = 0; mi < 2; mi++) {
#pragma unroll
        for (int ni = 0; ni < 8; ni++) {
            int row0 = bm + wm + mi * 16 + g;
            int col0 = bn + wn + ni * 8 + tg * 2;
            float b0 = bias ? bias[col0]     : 0.0f;
            float b1 = bias ? bias[col0 + 1] : 0.0f;
            *(float2*)&C[(size_t)row0 * ldc + col0] =
                make_float2(acc[mi][ni][0] + b0, acc[mi][ni][1] + b1);
            *(float2*)&C[(size_t)(row0 + 8) * ldc + col0] =
                make_float2(acc[mi][ni][2] + b0, acc[mi][ni][3] + b1);
        }
    }
}

// ---------------- 3-term FP16 split GEMM: ~fp32 accuracy ---------------------
// C = A @ B^T (+bias).  grid (N/128, M/128).  Dyn smem 65536.
__global__ void __launch_bounds__(256) gemm3h_kernel(
    const float* __restrict__ A, int lda,
    const float* __restrict__ B, int ldb,
    const float* __restrict__ bias,
    float* __restrict__ C, int ldc,
    int M, int N, int K)
{
    extern __shared__ char g3s[];
    __half* sAh = (__half*)g3s;
    __half* sAl = (__half*)(g3s + 16384);
    __half* sBh = (__half*)(g3s + 32768);
    __half* sBl = (__half*)(g3s + 49152);

    const int bm = blockIdx.y * 128;
    const int bn = blockIdx.x * 128;
    const int tid = threadIdx.x;
    const int warp = tid >> 5, lane = tid & 31;
    const int wm = (warp >> 1) * 32;
    const int wn = (warp & 1) * 64;
    const int g = lane >> 2, tg = lane & 3;

    float acc[2][8][4];
#pragma unroll
    for (int i = 0; i < 2; i++)
#pragma unroll
        for (int j = 0; j < 8; j++)
#pragma unroll
            for (int k = 0; k < 4; k++) acc[i][j][k] = 0.0f;

    for (int k0 = 0; k0 < K; k0 += 64) {
#pragma unroll
        for (int i = tid; i < 2048; i += 256) {
            int r = i >> 4, c4 = (i & 15) * 4;
            int off = r * 64 + (((c4 >> 3) ^ (r & 7)) << 3) + (c4 & 7);
            split_store4(sAh, sAl, off,
                *(const float4*)(A + (size_t)(bm + r) * lda + k0 + c4));
        }
#pragma unroll
        for (int i = tid; i < 2048; i += 256) {
            int r = i >> 4, c4 = (i & 15) * 4;
            int off = r * 64 + (((c4 >> 3) ^ (r & 7)) << 3) + (c4 & 7);
            split_store4(sBh, sBl, off,
                *(const float4*)(B + (size_t)(bn + r) * ldb + k0 + c4));
        }
        __syncthreads();

        const uint32_t* Ah32 = (const uint32_t*)sAh;
        const uint32_t* Al32 = (const uint32_t*)sAl;
        const uint32_t* Bh32 = (const uint32_t*)sBh;
        const uint32_t* Bl32 = (const uint32_t*)sBl;
#pragma unroll
        for (int kk = 0; kk < 64; kk += 16) {
            const int ch0 = kk >> 3, ch1 = ch0 + 1;
            unsigned ah[2][4], al[2][4], bh[8][2], bl[8][2];
#pragma unroll
            for (int mi = 0; mi < 2; mi++) {
                int r = wm + mi * 16 + g;
                int rw = r & 7;
                int base = r * 32;
                int o0 = ((ch0 ^ rw) << 2) + tg, o1 = ((ch1 ^ rw) << 2) + tg;
                ah[mi][0] = Ah32[base + o0];
                ah[mi][1] = Ah32[base + 256 + o0];
                ah[mi][2] = Ah32[base + o1];
                ah[mi][3] = Ah32[base + 256 + o1];
                al[mi][0] = Al32[base + o0];
                al[mi][1] = Al32[base + 256 + o0];
                al[mi][2] = Al32[base + o1];
                al[mi][3] = Al32[base + 256 + o1];
            }
#pragma unroll
            for (int ni = 0; ni < 8; ni++) {
                int c = wn + ni * 8 + g;
                int cw = c & 7;
                int cb = c * 32;
                int o0 = ((ch0 ^ cw) << 2) + tg, o1 = ((ch1 ^ cw) << 2) + tg;
                bh[ni][0] = Bh32[cb + o0];
                bh[ni][1] = Bh32[cb + o1];
                bl[ni][0] = Bl32[cb + o0];
                bl[ni][1] = Bl32[cb + o1];
            }
#pragma unroll
            for (int mi = 0; mi < 2; mi++)
#pragma unroll
                for (int ni = 0; ni < 8; ni++) {
                    mma_f16(acc[mi][ni], ah[mi], bh[ni]);
                    mma_f16(acc[mi][ni], al[mi], bh[ni]);
                    mma_f16(acc[mi][ni], ah[mi], bl[ni]);
                }
        }
        __syncthreads();
    }

#pragma unroll
    for (int mi = 0; mi < 2; mi++) {
#pragma unroll
        for (int ni = 0; ni < 8; ni++) {
            int row0 = bm + wm + mi * 16 + g;
            int col0 = bn + wn + ni * 8 + tg * 2;
            float b0 = bias ? bias[col0]     : 0.0f;
            float b1 = bias ? bias[col0 + 1] : 0.0f;
            *(float2*)&C[(size_t)row0 * ldc + col0] =
                make_float2(acc[mi][ni][0] + b0, acc[mi][ni][1] + b1);
            *(float2*)&C[(size_t)(row0 + 8) * ldc + col0] =
                make_float2(acc[mi][ni][2] + b0, acc[mi][ni][3] + b1);
        }
    }
}

// ---------------- persistent GRU (all 20 steps), H double-buffered -----------
__global__ void __launch_bounds__(256) gru_persist_kernel(
    const float* __restrict__ Whh, const float* __restrict__ bhh,
    const float* __restrict__ GI, const int* __restrict__ real_lens,
    float* __restrict__ feats, __half* __restrict__ Afh,
    float* __restrict__ hA, float* __restrict__ hB,
    __half* __restrict__ h16h, __half* __restrict__ h16l,
    unsigned* __restrict__ bar)
{
    extern __shared__ char ps[];
    __half* sWh = (__half*)ps;
    __half* sWl = (__half*)(ps + 24576);
    const uint32_t psb = (uint32_t)__cvta_generic_to_shared(ps);

    const int j0 = blockIdx.x * 8;
    const int tid = threadIdx.x;
    const int warp = tid >> 5, lane = tid & 31;
    const int g = lane >> 2, tg = lane & 3;

#pragma unroll
    for (int i = tid; i < 3072; i += 256) {
        int r = i >> 7, c4 = (i & 127) * 4;
        int grow = (r < 8) ? (j0 + r)
                 : (r < 16) ? (512 + j0 + r - 8)
                            : (1024 + j0 + r - 16);
        int q = c4 >> 6, c = c4 & 63;
        int off = q * 1536 + r * 64 + (((c >> 3) ^ (r & 7)) << 3) + (c & 7);
        split_store4(sWh, sWl, off, *(const float4*)(Whh + (size_t)grow * 512 + c4));
    }
    __syncthreads();

    const uint32_t* Wh32 = (const uint32_t*)sWh;
    const uint32_t* Wl32 = (const uint32_t*)sWl;

#define ISSUE_H(stg_, k0_) do {                                              \
        uint32_t hb_ = psb + 49152u + (uint32_t)(stg_) * 32768u;             \
        _Pragma("unroll")                                                    \
        for (int i_ = tid; i_ < 1024; i_ += 256) {                           \
            int r_ = i_ >> 3, c8_ = i_ & 7;                                  \
            uint32_t dsto_ = (uint32_t)((r_ * 64 + ((c8_ ^ (r_ & 7)) << 3)) * 2); \
            cp16(hb_ + dsto_, hih + r_ * 512 + (k0_) + c8_ * 8);             \
            cp16(hb_ + 16384u + dsto_, hil + r_ * 512 + (k0_) + c8_ * 8);    \
        }                                                                    \
        asm volatile("cp.async.commit_group;");                              \
    } while (0)

    for (int t = 0; t < T_; t++) {
        const int wsel = t & 1;
        float*  houtF = wsel ? hB : hA;
        const float* hinF = wsel ? hA : hB;
        __half* hoh = h16h + wsel * (B_ * H_);
        __half* hol = h16l + wsel * (B_ * H_);
        const __half* hih = h16h + (wsel ^ 1) * (B_ * H_);
        const __half* hil = h16l + (wsel ^ 1) * (B_ * H_);

        float acc[3][4] = {{0, 0, 0, 0}, {0, 0, 0, 0}, {0, 0, 0, 0}};

        if (t > 0) {
            ISSUE_H(0, 0);
            for (int c = 0; c < 8; c++) {
                if (c + 1 < 8) {
                    ISSUE_H((c + 1) & 1, (c + 1) * 64);
                    asm volatile("cp.async.wait_group 1;");
                } else {
                    asm volatile("cp.async.wait_group 0;");
                }
                __syncthreads();

                const uint32_t hb = 49152u + (uint32_t)(c & 1) * 32768u;
                const uint32_t* Hh32 = (const uint32_t*)(ps + hb);
                const uint32_t* Hl32 = (const uint32_t*)(ps + hb + 16384);
                const int q768 = c * 768;
#pragma unroll
                for (int kk = 0; kk < 64; kk += 16) {
                    const int ch0 = kk >> 3, ch1 = ch0 + 1;
                    unsigned ah[4], al[4];
                    int r = warp * 16 + g;
                    int rw = r & 7;
                    int base = r * 32;
                    int o0 = ((ch0 ^ rw) << 2) + tg, o1 = ((ch1 ^ rw) << 2) + tg;
                    ah[0] = Hh32[base + o0];
                    ah[1] = Hh32[base + 256 + o0];
                    ah[2] = Hh32[base + o1];
                    ah[3] = Hh32[base + 256 + o1];
                    al[0] = Hl32[base + o0];
                    al[1] = Hl32[base + 256 + o0];
                    al[2] = Hl32[base + o1];
                    al[3] = Hl32[base + 256 + o1];
#pragma unroll
                    for (int nt = 0; nt < 3; nt++) {
                        int cc = nt * 8 + g;
                        int cw = cc & 7;
                        int cb = q768 + cc * 32;
                        unsigned bh[2] = { Wh32[cb + ((ch0 ^ cw) << 2) + tg],
                                           Wh32[cb + ((ch1 ^ cw) << 2) + tg] };
                        unsigned bl[2] = { Wl32[cb + ((ch0 ^ cw) << 2) + tg],
                                           Wl32[cb + ((ch1 ^ cw) << 2) + tg] };
                        mma_f16(acc[nt], ah, bh);
                        mma_f16(acc[nt], al, bh);
                        mma_f16(acc[nt], ah, bl);
                    }
                }
                __syncthreads();
            }
        }

#pragma unroll
        for (int ri = 0; ri < 2; ri++) {
            int b = warp * 16 + g + ri * 8;
            const float* gib = GI + (size_t)(b * T_ + t) * (3 * H_);
            int rl = real_lens[b];
#pragma unroll
            for (int ci = 0; ci < 2; ci++) {
                int j = j0 + tg * 2 + ci;
                int ai = ri * 2 + ci;
                float ghr = acc[0][ai] + bhh[j];
                float ghz = acc[1][ai] + bhh[H_ + j];
                float ghn = acc[2][ai] + bhh[2 * H_ + j];
                float rr = sigmoidf_(gib[j] + ghr);
                float zz = sigmoidf_(gib[H_ + j] + ghz);
                float nn = tanhf(gib[2 * H_ + j] + rr * ghn);
                float hp = (t == 0) ? 0.0f : __ldcg(hinF + b * H_ + j);
                float hn = (1.0f - zz) * nn + zz * hp;
                houtF[b * H_ + j] = hn;
                __half hh = __float2half_rn(hn);
                hoh[b * H_ + j] = hh;
                hol[b * H_ + j] = __float2half_rn(hn - __half2float(hh));
                float mval = (t < rl) ? hn : 0.0f;
                size_t fo = (size_t)(b * T_ + t) * (2 * H_) + j;
                feats[fo] = mval;
                Afh[fo] = __float2half_rn(mval);
            }
        }

        if (t < T_ - 1) {
            __threadfence();
            __syncthreads();
            if (tid == 0) {
                atomicAdd(&bar[t], 1u);
                while (*((volatile unsigned*)&bar[t]) < 64u) {}
            }
            __syncthreads();
        }
    }
#undef ISSUE_H
}

// ---------------- top-k(5) + class-embedding mean (+ bar reset) --------------
__global__ void __launch_bounds__(256) topk_cls_kernel(
    const float* __restrict__ img, const float* __restrict__ cemb,
    float* __restrict__ cls, unsigned* __restrict__ bar)
{
    __shared__ float vals[NCLS];
    __shared__ float sval[256];
    __shared__ int   sidx[256];
    __shared__ int   win[TOPK];
    const int b = blockIdx.x, tid = threadIdx.x;

    if (b == 0 && tid < T_) bar[tid] = 0u;

    for (int i = tid; i < NCLS; i += 256) vals[i] = img[b * NCLS + i];
    __syncthreads();

    for (int r = 0; r < TOPK; r++) {
        float bv = -INFINITY;
        int bi = NCLS;
        for (int i = tid; i < NCLS; i += 256) {
            float v = vals[i];
            if (v > bv || (v == bv && i < bi)) { bv = v; bi = i; }
        }
        sval[tid] = bv; sidx[tid] = bi;
        __syncthreads();
        for (int s = 128; s > 0; s >>= 1) {
            if (tid < s) {
                float ov = sval[tid + s]; int oi = sidx[tid + s];
                if (ov > sval[tid] || (ov == sval[tid] && oi < sidx[tid])) {
                    sval[tid] = ov; sidx[tid] = oi;
                }
            }
            __syncthreads();
        }
        if (tid == 0) { win[r] = sidx[0]; vals[sidx[0]] = -INFINITY; }
        __syncthreads();
    }

    for (int d = tid; d < D_; d += 256) {
        float s = 0.0f;
#pragma unroll
        for (int j = 0; j < TOPK; j++) s += cemb[(size_t)win[j] * D_ + d];
        cls[b * D_ + d] = s * 0.2f;
    }
}

// ---------------- batchnorm over batch dim -----------------------------------
__global__ void __launch_bounds__(512) bn_kernel(
    float* __restrict__ proj, const float* __restrict__ gamma, const float* __restrict__ beta)
{
    const int d = threadIdx.x;
    float s = 0.0f, s2 = 0.0f;
    for (int b = 0; b < B_; b++) {
        float v = proj[b * D_ + d];
        s += v; s2 += v * v;
    }
    float mu  = s * (1.0f / B_);
    float var = s2 * (1.0f / B_) - mu * mu;
    float inv = rsqrtf(var + BN_EPS);
    float gm = gamma[d], bt = beta[d];
    for (int b = 0; b < B_; b++)
        proj[b * D_ + d] = (proj[b * D_ + d] - mu) * inv * gm + bt;
}

// ---------------- build GRU input matrix X -----------------------------------
__global__ void __launch_bounds__(256) build_x_kernel(
    const float* __restrict__ proj, const float* __restrict__ emb,
    const int* __restrict__ targets, float* __restrict__ X)
{
    int idx = blockIdx.x * 256 + threadIdx.x;
    int row = idx >> 9;
    int d   = idx & 511;
    int b = row / T_, t = row % T_;
    float v;
    if (t == 0) v = proj[b * D_ + d];
    else {
        int tok = targets[b * T_ + (t - 1)];
        v = emb[(size_t)tok * D_ + d];
    }
    X[(size_t)row * D_ + d] = v;
}

__global__ void __launch_bounds__(256) transpose_kernel(
    const float* __restrict__ W, float* __restrict__ WT)
{
    int idx = blockIdx.x * 256 + threadIdx.x;
    int e = idx >> 9, d = idx & 511;
    WT[e * H_ + d] = W[d * H_ + e];
}

// ---------------- causal bilinear attention (ct -> fp16 Afh right half) ------
__global__ void __launch_bounds__(256) attn_kernel(
    const float* __restrict__ feats, const float* __restrict__ u,
    __half* __restrict__ Afh)
{
    __shared__ float sc[T_][T_ + 1];
    const int b = blockIdx.x, tid = threadIdx.x;
    const int warp = tid >> 5, lane = tid & 31;
    const float* outb = feats + (size_t)b * T_ * (2 * H_);
    const float* ub   = u     + (size_t)b * T_ * H_;

    for (int p = warp; p < (T_ * (T_ - 1)) / 2; p += 8) {
        int t = 1;
        while ((t + 1) * t / 2 <= p) t++;
        int s = p - t * (t - 1) / 2;
        float acc = 0.0f;
        for (int k = lane; k < H_; k += 32)
            acc += ub[t * H_ + k] * outb[(size_t)s * (2 * H_) + k];
#pragma unroll
        for (int off = 16; off > 0; off >>= 1)
            acc += __shfl_xor_sync(0xFFFFFFFF, acc, off);
        if (lane == 0) sc[t][s] = acc;
    }
    __syncthreads();

    if (tid >= 1 && tid < T_) {
        int t = tid;
        float mx = -INFINITY;
        for (int s = 0; s < t; s++) mx = fmaxf(mx, sc[t][s]);
        float sum = 0.0f;
        for (int s = 0; s < t; s++) { float e = expf(sc[t][s] - mx); sc[t][s] = e; sum += e; }
        float inv = 1.0f / sum;
        for (int s = 0; s < t; s++) sc[t][s] *= inv;
    }
    __syncthreads();

    for (int idx = tid; idx < T_ * H_; idx += 256) {
        int t = idx >> 9;
        int hh = idx & 511;
        float acc = 0.0f;
        for (int s = 0; s < t; s++)
            acc += sc[t][s] * outb[(size_t)s * (2 * H_) + hh];
        Afh[(size_t)b * T_ * (2 * H_) + (size_t)t * (2 * H_) + H_ + hh] =
            __float2half_rn(acc);
    }
}

// ---------------- launch -----------------------------------------------------
#define VG_SMEM 147456
#define G3_SMEM 65536
#define GP_SMEM 114688

extern "C" void kernel_launch(void* const* d_in, const int* in_sizes, int n_in,
                              void* d_out, int out_size)
{
    (void)in_sizes; (void)n_in; (void)out_size;
    const float* img_rep   = (const float*)d_in[0];
    const int*   targets   = (const int*)d_in[1];
    const int*   real_lens = (const int*)d_in[2];
    const float* class_emb = (const float*)d_in[3];
    const float* proj_W    = (const float*)d_in[4];
    const float* proj_b    = (const float*)d_in[5];
    const float* bn_gamma  = (const float*)d_in[6];
    const float* bn_beta   = (const float*)d_in[7];
    const float* emb_table = (const float*)d_in[8];
    const float* gru_Wih   = (const float*)d_in[9];
    const float* gru_Whh   = (const float*)d_in[10];
    const float* gru_bih   = (const float*)d_in[11];
    const float* gru_bhh   = (const float*)d_in[12];
    const float* attn_W    = (const float*)d_in[13];
    const float* vocab_W   = (const float*)d_in[14];
    const float* vocab_b   = (const float*)d_in[15];
    float* out = (float*)d_out;

    float *cls, *proj, *X, *GI, *h0, *h1, *feats, *u, *attn_WT;
    __half *Afh, *Bvh, *h16h, *h16l;
    unsigned* bar;
    cudaGetSymbolAddress((void**)&cls,     d_cls);
    cudaGetSymbolAddress((void**)&proj,    d_proj);
    cudaGetSymbolAddress((void**)&X,       d_X);
    cudaGetSymbolAddress((void**)&GI,      d_GI);
    cudaGetSymbolAddress((void**)&h0,      d_h0);
    cudaGetSymbolAddress((void**)&h1,      d_h1);
    cudaGetSymbolAddress((void**)&feats,   d_feats);
    cudaGetSymbolAddress((void**)&u,       d_u);
    cudaGetSymbolAddress((void**)&attn_WT, d_attn_WT);
    cudaGetSymbolAddress((void**)&Afh,     d_Afh);
    cudaGetSymbolAddress((void**)&Bvh,     d_Bvh);
    cudaGetSymbolAddress((void**)&h16h,    d_h16h);
    cudaGetSymbolAddress((void**)&h16l,    d_h16l);
    cudaGetSymbolAddress((void**)&bar,     d_bar);

    cudaFuncSetAttribute(vgemm256_kernel,
                         cudaFuncAttributeMaxDynamicSharedMemorySize, VG_SMEM);
    cudaFuncSetAttribute(gemm3h_kernel,
                         cudaFuncAttributeMaxDynamicSharedMemorySize, G3_SMEM);
    cudaFuncSetAttribute(gru_persist_kernel,
                         cudaFuncAttributeMaxDynamicSharedMemorySize, GP_SMEM);

    // (1) image -> class embedding mean  (also resets GRU barrier counters)
    topk_cls_kernel<<<B_, 256>>>(img_rep, class_emb, cls, bar);

    // (2) proj = cls @ proj_W^T + b   (fp16 3-term)
    gemm3h_kernel<<<dim3(D_ / 128, B_ / 128), 256, G3_SMEM>>>(
        cls, D_, proj_W, D_, proj_b, proj, D_, B_, D_, D_);

    // (3) batchnorm (train mode) in place
    bn_kernel<<<1, D_>>>(proj, bn_gamma, bn_beta);

    // (4) vocab_W -> fp16
    f2h_kernel<<<1184, 256>>>(vocab_W, Bvh, V_ * 2 * H_ / 4);

    // (5) build X (B*T, D)
    build_x_kernel<<<(B_ * T_ * D_) / 256, 256>>>(proj, emb_table, targets, X);

    // (6) GI = X @ Wih^T + bih  (fp16 3-term)
    gemm3h_kernel<<<dim3((3 * H_) / 128, (B_ * T_) / 128), 256, G3_SMEM>>>(
        X, D_, gru_Wih, D_, gru_bih, GI, 3 * H_, B_ * T_, 3 * H_, D_);

    // (7) transpose attn_W
    transpose_kernel<<<(H_ * H_) / 256, 256>>>(attn_W, attn_WT);

    // (8) persistent GRU (H loads double-buffered; writes f32 feats + fp16 Afh)
    gru_persist_kernel<<<64, 256, GP_SMEM>>>(
        gru_Whh, gru_bhh, GI, real_lens, feats, Afh, h0, h1, h16h, h16l, bar);

    // (9) u = out @ attn_W  (fp16 3-term via transposed weights)
    gemm3h_kernel<<<dim3(H_ / 128, (B_ * T_) / 128), 256, G3_SMEM>>>(
        feats, 2 * H_, attn_WT, H_, nullptr, u, H_, B_ * T_, H_, H_);

    // (10) causal attention -> ct written as fp16 directly into Afh right half
    attn_kernel<<<B_, 256>>>(feats, u, Afh);

    // (11) logits = Afh @ Bvh^T + vocab_b  (fp16, 128x256 tile kernel)
    vgemm256_kernel<<<dim3((B_ * T_) / 128, V_ / 256), 512, VG_SMEM>>>(
        Afh, Bvh, vocab_b, out, 2 * H_, V_);
}

// round 16
// speedup vs baseline: 1.0561x; 1.0561x over previous
#include <cuda_runtime.h>
#include <cuda_fp16.h>
#include <cstdint>
#include <math.h>

// Problem constants
#define B_   128
#define T_   20
#define D_   512
#define H_   512
#define V_   32000
#define NCLS 1000
#define TOPK 5
#define BN_EPS 1e-5f

// ---------------- scratch (device globals; no allocation allowed) ----------
__device__ float d_cls[B_ * D_];
__device__ float d_proj[B_ * D_];
__device__ float d_X[B_ * T_ * D_];
__device__ float d_GI[B_ * T_ * 3 * H_];
__device__ float d_h0[B_ * H_];
__device__ float d_h1[B_ * H_];
__device__ __half d_h16h[2 * B_ * H_];
__device__ __half d_h16l[2 * B_ * H_];
__device__ unsigned d_bar[T_];
__device__ float d_feats[B_ * T_ * 2 * H_];
__device__ float d_u[B_ * T_ * H_];
__device__ float d_attn_WT[H_ * H_];
__device__ __half d_Afh[B_ * T_ * 2 * H_];
__device__ __half d_Bvh[(size_t)V_ * 2 * H_];

// ---------------- helpers ---------------------------------------------------
__device__ __forceinline__ void mma_f16(float* c, const unsigned* a, const unsigned* b) {
    asm volatile(
        "mma.sync.aligned.m16n8k16.row.col.f32.f16.f16.f32 "
        "{%0,%1,%2,%3}, {%4,%5,%6,%7}, {%8,%9}, {%0,%1,%2,%3};"
        : "+f"(c[0]), "+f"(c[1]), "+f"(c[2]), "+f"(c[3])
        : "r"(a[0]), "r"(a[1]), "r"(a[2]), "r"(a[3]), "r"(b[0]), "r"(b[1]));
}
__device__ __forceinline__ void ldsm_x4(unsigned* r, uint32_t addr) {
    asm volatile(
        "ldmatrix.sync.aligned.m8n8.x4.shared.b16 {%0,%1,%2,%3}, [%4];"
        : "=r"(r[0]), "=r"(r[1]), "=r"(r[2]), "=r"(r[3]) : "r"(addr));
}
__device__ __forceinline__ float sigmoidf_(float x) { return 1.0f / (1.0f + expf(-x)); }

__device__ __forceinline__ void cp16(uint32_t dst, const void* src) {
    asm volatile("cp.async.cg.shared.global [%0], [%1], 16;" :: "r"(dst), "l"(src));
}

// split f32 -> (hi, lo) halves and store 4-wide at smem offset (half units)
__device__ __forceinline__ void split_store4(
    __half* hiP, __half* loP, int off, float4 v)
{
    __half h0 = __float2half_rn(v.x), h1 = __float2half_rn(v.y);
    __half h2 = __float2half_rn(v.z), h3 = __float2half_rn(v.w);
    __half l0 = __float2half_rn(v.x - __half2float(h0));
    __half l1 = __float2half_rn(v.y - __half2float(h1));
    __half l2 = __float2half_rn(v.z - __half2float(h2));
    __half l3 = __float2half_rn(v.w - __half2float(h3));
    __half2 a0 = __halves2half2(h0, h1), a1 = __halves2half2(h2, h3);
    __half2 b0 = __halves2half2(l0, l1), b1 = __halves2half2(l2, l3);
    uint2 hv, lv;
    hv.x = *(unsigned*)&a0; hv.y = *(unsigned*)&a1;
    lv.x = *(unsigned*)&b0; lv.y = *(unsigned*)&b1;
    *(uint2*)(hiP + off) = hv;
    *(uint2*)(loP + off) = lv;
}

// ---------------- f32 -> f16 conversion (grid-stride, 8B stores) -------------
__global__ void __launch_bounds__(256) f2h_kernel(
    const float* __restrict__ src, __half* __restrict__ dst, int n4)
{
    const int stride = gridDim.x * 256;
    for (int i = blockIdx.x * 256 + threadIdx.x; i < n4; i += stride) {
        float4 v = ((const float4*)src)[i];
        __half2 lo = __floats2half2_rn(v.x, v.y);
        __half2 hi = __floats2half2_rn(v.z, v.w);
        uint2 o;
        o.x = *(unsigned*)&lo;
        o.y = *(unsigned*)&hi;
        ((uint2*)dst)[i] = o;
    }
}

// ---------------- 512-thread FP16 GEMM (vocab): 16 warps, 32x32 warp tile ----
// C = A @ B^T + bias.  A (M,K) half, B (N,K) half, C (M,N) f32.
// grid = (M/128, N/128), M fastest.  3-stage cp.async, 98304 B dyn smem.
// Epilogue uses streaming stores (.cs) so the 327 MB output doesn't evict
// the L2-resident vocab_W tiles shared across the wave.
__global__ void __launch_bounds__(512, 2) vgemm512_kernel(
    const __half* __restrict__ A, const __half* __restrict__ Bm,
    const float* __restrict__ bias, float* __restrict__ C,
    int K, int ldc)
{
    extern __shared__ char hs[];

    const int bm = blockIdx.x * 128;
    const int bn = blockIdx.y * 128;
    const int tid = threadIdx.x;
    const int warp = tid >> 5, lane = tid & 31;
    const int wm = (warp >> 2) * 32;
    const int wn = (warp & 3) * 32;
    const int g = lane >> 2, tg = lane & 3;

    const int lr  = tid >> 2;
    const int lc0 = (tid & 3) * 2;
    const int rs  = lr & 7;
    const __half* gA = A + (size_t)(bm + lr) * K + lc0 * 8;
    const __half* gB = Bm + (size_t)(bn + lr) * K + lc0 * 8;
    const uint32_t sbase = (uint32_t)__cvta_generic_to_shared(hs);
    const uint32_t sA = sbase + lr * 128;
    const uint32_t sB = sA + 16384;

    const int arow = ((lane >> 3) & 1) * 8 + (lane & 7);
    const int ako  = lane >> 4;
    const int axor = lane & 7;
    const int brow = ((lane >> 4) << 3) + (lane & 7);
    const int bko  = (lane >> 3) & 1;
    const int bxor = lane & 7;
    uint32_t aoff[2], boff[2];
#pragma unroll
    for (int mi = 0; mi < 2; mi++) aoff[mi] = (uint32_t)((wm + mi * 16 + arow) * 128);
#pragma unroll
    for (int nj = 0; nj < 2; nj++) boff[nj] = (uint32_t)(16384 + (wn + nj * 16 + brow) * 128);

#define HISSUE(st_, k0_) do {                                        \
        uint32_t o_ = (uint32_t)(st_) * 32768u;                      \
        _Pragma("unroll")                                            \
        for (int c_ = 0; c_ < 2; c_++) {                             \
            uint32_t sw_ = (uint32_t)(((lc0 + c_) ^ rs) << 4);       \
            cp16(sA + o_ + sw_, gA + (k0_) + c_ * 8);                \
            cp16(sB + o_ + sw_, gB + (k0_) + c_ * 8);                \
        }                                                            \
        asm volatile("cp.async.commit_group;");                      \
    } while (0)

    const int niter = K >> 6;
    HISSUE(0, 0);
    HISSUE(1, 64);

    float acc[2][4][4];
#pragma unroll
    for (int i = 0; i < 2; i++)
#pragma unroll
        for (int j = 0; j < 4; j++)
#pragma unroll
            for (int k = 0; k < 4; k++) acc[i][j][k] = 0.0f;

    for (int it = 0; it < niter; it++) {
        if (it + 1 < niter) asm volatile("cp.async.wait_group 1;");
        else                asm volatile("cp.async.wait_group 0;");
        __syncthreads();
        if (it + 2 < niter) HISSUE((it + 2) % 3, (it + 2) * 64);

        const uint32_t st = sbase + (uint32_t)(it % 3) * 32768u;
#pragma unroll
        for (int kk = 0; kk < 64; kk += 16) {
            const int ch0 = kk >> 3;
            unsigned a[2][4], bq[2][4];
#pragma unroll
            for (int mi = 0; mi < 2; mi++)
                ldsm_x4(a[mi], st + aoff[mi] + (uint32_t)((((ch0 + ako) ^ axor)) << 4));
#pragma unroll
            for (int nj = 0; nj < 2; nj++)
                ldsm_x4(bq[nj], st + boff[nj] + (uint32_t)((((ch0 + bko) ^ bxor)) << 4));
#pragma unroll
            for (int mi = 0; mi < 2; mi++)
#pragma unroll
                for (int nj = 0; nj < 2; nj++) {
                    mma_f16(acc[mi][2 * nj],     a[mi], &bq[nj][0]);
                    mma_f16(acc[mi][2 * nj + 1], a[mi], &bq[nj][2]);
                }
        }
        __syncthreads();
    }
#undef HISSUE

#pragma unroll
    for (int mi = 0; mi < 2; mi++) {
#pragma unroll
        for (int ni = 0; ni < 4; ni++) {
            int row0 = bm + wm + mi * 16 + g;
            int col0 = bn + wn + ni * 8 + tg * 2;
            float b0 = bias ? bias[col0]     : 0.0f;
            float b1 = bias ? bias[col0 + 1] : 0.0f;
            __stcs((float2*)&C[(size_t)row0 * ldc + col0],
                   make_float2(acc[mi][ni][0] + b0, acc[mi][ni][1] + b1));
            __stcs((float2*)&C[(size_t)(row0 + 8) * ldc + col0],
                   make_float2(acc[mi][ni][2] + b0, acc[mi][ni][3] + b1));
        }
    }
}

// ---------------- 3-term FP16 split GEMM: ~fp32 accuracy ---------------------
// C = A @ B^T (+bias).  grid (N/128, M/128).  Dyn smem 65536.
__global__ void __launch_bounds__(256) gemm3h_kernel(
    const float* __restrict__ A, int lda,
    const float* __restrict__ B, int ldb,
    const float* __restrict__ bias,
    float* __restrict__ C, int ldc,
    int M, int N, int K)
{
    extern __shared__ char g3s[];
    __half* sAh = (__half*)g3s;
    __half* sAl = (__half*)(g3s + 16384);
    __half* sBh = (__half*)(g3s + 32768);
    __half* sBl = (__half*)(g3s + 49152);

    const int bm = blockIdx.y * 128;
    const int bn = blockIdx.x * 128;
    const int tid = threadIdx.x;
    const int warp = tid >> 5, lane = tid & 31;
    const int wm = (warp >> 1) * 32;
    const int wn = (warp & 1) * 64;
    const int g = lane >> 2, tg = lane & 3;

    float acc[2][8][4];
#pragma unroll
    for (int i = 0; i < 2; i++)
#pragma unroll
        for (int j = 0; j < 8; j++)
#pragma unroll
            for (int k = 0; k < 4; k++) acc[i][j][k] = 0.0f;

    for (int k0 = 0; k0 < K; k0 += 64) {
#pragma unroll
        for (int i = tid; i < 2048; i += 256) {
            int r = i >> 4, c4 = (i & 15) * 4;
            int off = r * 64 + (((c4 >> 3) ^ (r & 7)) << 3) + (c4 & 7);
            split_store4(sAh, sAl, off,
                *(const float4*)(A + (size_t)(bm + r) * lda + k0 + c4));
        }
#pragma unroll
        for (int i = tid; i < 2048; i += 256) {
            int r = i >> 4, c4 = (i & 15) * 4;
            int off = r * 64 + (((c4 >> 3) ^ (r & 7)) << 3) + (c4 & 7);
            split_store4(sBh, sBl, off,
                *(const float4*)(B + (size_t)(bn + r) * ldb + k0 + c4));
        }
        __syncthreads();

        const uint32_t* Ah32 = (const uint32_t*)sAh;
        const uint32_t* Al32 = (const uint32_t*)sAl;
        const uint32_t* Bh32 = (const uint32_t*)sBh;
        const uint32_t* Bl32 = (const uint32_t*)sBl;
#pragma unroll
        for (int kk = 0; kk < 64; kk += 16) {
            const int ch0 = kk >> 3, ch1 = ch0 + 1;
            unsigned ah[2][4], al[2][4], bh[8][2], bl[8][2];
#pragma unroll
            for (int mi = 0; mi < 2; mi++) {
                int r = wm + mi * 16 + g;
                int rw = r & 7;
                int base = r * 32;
                int o0 = ((ch0 ^ rw) << 2) + tg, o1 = ((ch1 ^ rw) << 2) + tg;
                ah[mi][0] = Ah32[base + o0];
                ah[mi][1] = Ah32[base + 256 + o0];
                ah[mi][2] = Ah32[base + o1];
                ah[mi][3] = Ah32[base + 256 + o1];
                al[mi][0] = Al32[base + o0];
                al[mi][1] = Al32[base + 256 + o0];
                al[mi][2] = Al32[base + o1];
                al[mi][3] = Al32[base + 256 + o1];
            }
#pragma unroll
            for (int ni = 0; ni < 8; ni++) {
                int c = wn + ni * 8 + g;
                int cw = c & 7;
                int cb = c * 32;
                int o0 = ((ch0 ^ cw) << 2) + tg, o1 = ((ch1 ^ cw) << 2) + tg;
                bh[ni][0] = Bh32[cb + o0];
                bh[ni][1] = Bh32[cb + o1];
                bl[ni][0] = Bl32[cb + o0];
                bl[ni][1] = Bl32[cb + o1];
            }
#pragma unroll
            for (int mi = 0; mi < 2; mi++)
#pragma unroll
                for (int ni = 0; ni < 8; ni++) {
                    mma_f16(acc[mi][ni], ah[mi], bh[ni]);
                    mma_f16(acc[mi][ni], al[mi], bh[ni]);
                    mma_f16(acc[mi][ni], ah[mi], bl[ni]);
                }
        }
        __syncthreads();
    }

#pragma unroll
    for (int mi = 0; mi < 2; mi++) {
#pragma unroll
        for (int ni = 0; ni < 8; ni++) {
            int row0 = bm + wm + mi * 16 + g;
            int col0 = bn + wn + ni * 8 + tg * 2;
            float b0 = bias ? bias[col0]     : 0.0f;
            float b1 = bias ? bias[col0 + 1] : 0.0f;
            *(float2*)&C[(size_t)row0 * ldc + col0] =
                make_float2(acc[mi][ni][0] + b0, acc[mi][ni][1] + b1);
            *(float2*)&C[(size_t)(row0 + 8) * ldc + col0] =
                make_float2(acc[mi][ni][2] + b0, acc[mi][ni][3] + b1);
        }
    }
}

// ---------------- persistent GRU (all 20 steps), H double-buffered -----------
__global__ void __launch_bounds__(256) gru_persist_kernel(
    const float* __restrict__ Whh, const float* __restrict__ bhh,
    const float* __restrict__ GI, const int* __restrict__ real_lens,
    float* __restrict__ feats, __half* __restrict__ Afh,
    float* __restrict__ hA, float* __restrict__ hB,
    __half* __restrict__ h16h, __half* __restrict__ h16l,
    unsigned* __restrict__ bar)
{
    extern __shared__ char ps[];
    __half* sWh = (__half*)ps;
    __half* sWl = (__half*)(ps + 24576);
    const uint32_t psb = (uint32_t)__cvta_generic_to_shared(ps);

    const int j0 = blockIdx.x * 8;
    const int tid = threadIdx.x;
    const int warp = tid >> 5, lane = tid & 31;
    const int g = lane >> 2, tg = lane & 3;

#pragma unroll
    for (int i = tid; i < 3072; i += 256) {
        int r = i >> 7, c4 = (i & 127) * 4;
        int grow = (r < 8) ? (j0 + r)
                 : (r < 16) ? (512 + j0 + r - 8)
                            : (1024 + j0 + r - 16);
        int q = c4 >> 6, c = c4 & 63;
        int off = q * 1536 + r * 64 + (((c >> 3) ^ (r & 7)) << 3) + (c & 7);
        split_store4(sWh, sWl, off, *(const float4*)(Whh + (size_t)grow * 512 + c4));
    }
    __syncthreads();

    const uint32_t* Wh32 = (const uint32_t*)sWh;
    const uint32_t* Wl32 = (const uint32_t*)sWl;

#define ISSUE_H(stg_, k0_) do {                                              \
        uint32_t hb_ = psb + 49152u + (uint32_t)(stg_) * 32768u;             \
        _Pragma("unroll")                                                    \
        for (int i_ = tid; i_ < 1024; i_ += 256) {                           \
            int r_ = i_ >> 3, c8_ = i_ & 7;                                  \
            uint32_t dsto_ = (uint32_t)((r_ * 64 + ((c8_ ^ (r_ & 7)) << 3)) * 2); \
            cp16(hb_ + dsto_, hih + r_ * 512 + (k0_) + c8_ * 8);             \
            cp16(hb_ + 16384u + dsto_, hil + r_ * 512 + (k0_) + c8_ * 8);    \
        }                                                                    \
        asm volatile("cp.async.commit_group;");                              \
    } while (0)

    for (int t = 0; t < T_; t++) {
        const int wsel = t & 1;
        float*  houtF = wsel ? hB : hA;
        const float* hinF = wsel ? hA : hB;
        __half* hoh = h16h + wsel * (B_ * H_);
        __half* hol = h16l + wsel * (B_ * H_);
        const __half* hih = h16h + (wsel ^ 1) * (B_ * H_);
        const __half* hil = h16l + (wsel ^ 1) * (B_ * H_);

        float acc[3][4] = {{0, 0, 0, 0}, {0, 0, 0, 0}, {0, 0, 0, 0}};

        if (t > 0) {
            ISSUE_H(0, 0);
            for (int c = 0; c < 8; c++) {
                if (c + 1 < 8) {
                    ISSUE_H((c + 1) & 1, (c + 1) * 64);
                    asm volatile("cp.async.wait_group 1;");
                } else {
                    asm volatile("cp.async.wait_group 0;");
                }
                __syncthreads();

                const uint32_t hb = 49152u + (uint32_t)(c & 1) * 32768u;
                const uint32_t* Hh32 = (const uint32_t*)(ps + hb);
                const uint32_t* Hl32 = (const uint32_t*)(ps + hb + 16384);
                const int q768 = c * 768;
#pragma unroll
                for (int kk = 0; kk < 64; kk += 16) {
                    const int ch0 = kk >> 3, ch1 = ch0 + 1;
                    unsigned ah[4], al[4];
                    int r = warp * 16 + g;
                    int rw = r & 7;
                    int base = r * 32;
                    int o0 = ((ch0 ^ rw) << 2) + tg, o1 = ((ch1 ^ rw) << 2) + tg;
                    ah[0] = Hh32[base + o0];
                    ah[1] = Hh32[base + 256 + o0];
                    ah[2] = Hh32[base + o1];
                    ah[3] = Hh32[base + 256 + o1];
                    al[0] = Hl32[base + o0];
                    al[1] = Hl32[base + 256 + o0];
                    al[2] = Hl32[base + o1];
                    al[3] = Hl32[base + 256 + o1];
#pragma unroll
                    for (int nt = 0; nt < 3; nt++) {
                        int cc = nt * 8 + g;
                        int cw = cc & 7;
                        int cb = q768 + cc * 32;
                        unsigned bh[2] = { Wh32[cb + ((ch0 ^ cw) << 2) + tg],
                                           Wh32[cb + ((ch1 ^ cw) << 2) + tg] };
                        unsigned bl[2] = { Wl32[cb + ((ch0 ^ cw) << 2) + tg],
                                           Wl32[cb + ((ch1 ^ cw) << 2) + tg] };
                        mma_f16(acc[nt], ah, bh);
                        mma_f16(acc[nt], al, bh);
                        mma_f16(acc[nt], ah, bl);
                    }
                }
                __syncthreads();
            }
        }

#pragma unroll
        for (int ri = 0; ri < 2; ri++) {
            int b = warp * 16 + g + ri * 8;
            const float* gib = GI + (size_t)(b * T_ + t) * (3 * H_);
            int rl = real_lens[b];
#pragma unroll
            for (int ci = 0; ci < 2; ci++) {
                int j = j0 + tg * 2 + ci;
                int ai = ri * 2 + ci;
                float ghr = acc[0][ai] + bhh[j];
                float ghz = acc[1][ai] + bhh[H_ + j];
                float ghn = acc[2][ai] + bhh[2 * H_ + j];
                float rr = sigmoidf_(gib[j] + ghr);
                float zz = sigmoidf_(gib[H_ + j] + ghz);
                float nn = tanhf(gib[2 * H_ + j] + rr * ghn);
                float hp = (t == 0) ? 0.0f : __ldcg(hinF + b * H_ + j);
                float hn = (1.0f - zz) * nn + zz * hp;
                houtF[b * H_ + j] = hn;
                __half hh = __float2half_rn(hn);
                hoh[b * H_ + j] = hh;
                hol[b * H_ + j] = __float2half_rn(hn - __half2float(hh));
                float mval = (t < rl) ? hn : 0.0f;
                size_t fo = (size_t)(b * T_ + t) * (2 * H_) + j;
                feats[fo] = mval;
                Afh[fo] = __float2half_rn(mval);
            }
        }

        if (t < T_ - 1) {
            __threadfence();
            __syncthreads();
            if (tid == 0) {
                atomicAdd(&bar[t], 1u);
                while (*((volatile unsigned*)&bar[t]) < 64u) {}
            }
            __syncthreads();
        }
    }
#undef ISSUE_H
}

// ---------------- top-k(5) + class-embedding mean (+ bar reset) --------------
__global__ void __launch_bounds__(256) topk_cls_kernel(
    const float* __restrict__ img, const float* __restrict__ cemb,
    float* __restrict__ cls, unsigned* __restrict__ bar)
{
    __shared__ float vals[NCLS];
    __shared__ float sval[256];
    __shared__ int   sidx[256];
    __shared__ int   win[TOPK];
    const int b = blockIdx.x, tid = threadIdx.x;

    if (b == 0 && tid < T_) bar[tid] = 0u;

    for (int i = tid; i < NCLS; i += 256) vals[i] = img[b * NCLS + i];
    __syncthreads();

    for (int r = 0; r < TOPK; r++) {
        float bv = -INFINITY;
        int bi = NCLS;
        for (int i = tid; i < NCLS; i += 256) {
            float v = vals[i];
            if (v > bv || (v == bv && i < bi)) { bv = v; bi = i; }
        }
        sval[tid] = bv; sidx[tid] = bi;
        __syncthreads();
        for (int s = 128; s > 0; s >>= 1) {
            if (tid < s) {
                float ov = sval[tid + s]; int oi = sidx[tid + s];
                if (ov > sval[tid] || (ov == sval[tid] && oi < sidx[tid])) {
                    sval[tid] = ov; sidx[tid] = oi;
                }
            }
            __syncthreads();
        }
        if (tid == 0) { win[r] = sidx[0]; vals[sidx[0]] = -INFINITY; }
        __syncthreads();
    }

    for (int d = tid; d < D_; d += 256) {
        float s = 0.0f;
#pragma unroll
        for (int j = 0; j < TOPK; j++) s += cemb[(size_t)win[j] * D_ + d];
        cls[b * D_ + d] = s * 0.2f;
    }
}

// ---------------- batchnorm over batch dim -----------------------------------
__global__ void __launch_bounds__(512) bn_kernel(
    float* __restrict__ proj, const float* __restrict__ gamma, const float* __restrict__ beta)
{
    const int d = threadIdx.x;
    float s = 0.0f, s2 = 0.0f;
    for (int b = 0; b < B_; b++) {
        float v = proj[b * D_ + d];
        s += v; s2 += v * v;
    }
    float mu  = s * (1.0f / B_);
    float var = s2 * (1.0f / B_) - mu * mu;
    float inv = rsqrtf(var + BN_EPS);
    float gm = gamma[d], bt = beta[d];
    for (int b = 0; b < B_; b++)
        proj[b * D_ + d] = (proj[b * D_ + d] - mu) * inv * gm + bt;
}

// ---------------- build GRU input matrix X -----------------------------------
__global__ void __launch_bounds__(256) build_x_kernel(
    const float* __restrict__ proj, const float* __restrict__ emb,
    const int* __restrict__ targets, float* __restrict__ X)
{
    int idx = blockIdx.x * 256 + threadIdx.x;
    int row = idx >> 9;
    int d   = idx & 511;
    int b = row / T_, t = row % T_;
    float v;
    if (t == 0) v = proj[b * D_ + d];
    else {
        int tok = targets[b * T_ + (t - 1)];
        v = emb[(size_t)tok * D_ + d];
    }
    X[(size_t)row * D_ + d] = v;
}

__global__ void __launch_bounds__(256) transpose_kernel(
    const float* __restrict__ W, float* __restrict__ WT)
{
    int idx = blockIdx.x * 256 + threadIdx.x;
    int e = idx >> 9, d = idx & 511;
    WT[e * H_ + d] = W[d * H_ + e];
}

// ---------------- causal bilinear attention (ct -> fp16 Afh right half) ------
__global__ void __launch_bounds__(256) attn_kernel(
    const float* __restrict__ feats, const float* __restrict__ u,
    __half* __restrict__ Afh)
{
    __shared__ float sc[T_][T_ + 1];
    const int b = blockIdx.x, tid = threadIdx.x;
    const int warp = tid >> 5, lane = tid & 31;
    const float* outb = feats + (size_t)b * T_ * (2 * H_);
    const float* ub   = u     + (size_t)b * T_ * H_;

    for (int p = warp; p < (T_ * (T_ - 1)) / 2; p += 8) {
        int t = 1;
        while ((t + 1) * t / 2 <= p) t++;
        int s = p - t * (t - 1) / 2;
        float acc = 0.0f;
        for (int k = lane; k < H_; k += 32)
            acc += ub[t * H_ + k] * outb[(size_t)s * (2 * H_) + k];
#pragma unroll
        for (int off = 16; off > 0; off >>= 1)
            acc += __shfl_xor_sync(0xFFFFFFFF, acc, off);
        if (lane == 0) sc[t][s] = acc;
    }
    __syncthreads();

    if (tid >= 1 && tid < T_) {
        int t = tid;
        float mx = -INFINITY;
        for (int s = 0; s < t; s++) mx = fmaxf(mx, sc[t][s]);
        float sum = 0.0f;
        for (int s = 0; s < t; s++) { float e = expf(sc[t][s] - mx); sc[t][s] = e; sum += e; }
        float inv = 1.0f / sum;
        for (int s = 0; s < t; s++) sc[t][s] *= inv;
    }
    __syncthreads();

    for (int idx = tid; idx < T_ * H_; idx += 256) {
        int t = idx >> 9;
        int hh = idx & 511;
        float acc = 0.0f;
        for (int s = 0; s < t; s++)
            acc += sc[t][s] * outb[(size_t)s * (2 * H_) + hh];
        Afh[(size_t)b * T_ * (2 * H_) + (size_t)t * (2 * H_) + H_ + hh] =
            __float2half_rn(acc);
    }
}

// ---------------- launch -----------------------------------------------------
#define VG_SMEM 98304
#define G3_SMEM 65536
#define GP_SMEM 114688

extern "C" void kernel_launch(void* const* d_in, const int* in_sizes, int n_in,
                              void* d_out, int out_size)
{
    (void)in_sizes; (void)n_in; (void)out_size;
    const float* img_rep   = (const float*)d_in[0];
    const int*   targets   = (const int*)d_in[1];
    const int*   real_lens = (const int*)d_in[2];
    const float* class_emb = (const float*)d_in[3];
    const float* proj_W    = (const float*)d_in[4];
    const float* proj_b    = (const float*)d_in[5];
    const float* bn_gamma  = (const float*)d_in[6];
    const float* bn_beta   = (const float*)d_in[7];
    const float* emb_table = (const float*)d_in[8];
    const float* gru_Wih   = (const float*)d_in[9];
    const float* gru_Whh   = (const float*)d_in[10];
    const float* gru_bih   = (const float*)d_in[11];
    const float* gru_bhh   = (const float*)d_in[12];
    const float* attn_W    = (const float*)d_in[13];
    const float* vocab_W   = (const float*)d_in[14];
    const float* vocab_b   = (const float*)d_in[15];
    float* out = (float*)d_out;

    float *cls, *proj, *X, *GI, *h0, *h1, *feats, *u, *attn_WT;
    __half *Afh, *Bvh, *h16h, *h16l;
    unsigned* bar;
    cudaGetSymbolAddress((void**)&cls,     d_cls);
    cudaGetSymbolAddress((void**)&proj,    d_proj);
    cudaGetSymbolAddress((void**)&X,       d_X);
    cudaGetSymbolAddress((void**)&GI,      d_GI);
    cudaGetSymbolAddress((void**)&h0,      d_h0);
    cudaGetSymbolAddress((void**)&h1,      d_h1);
    cudaGetSymbolAddress((void**)&feats,   d_feats);
    cudaGetSymbolAddress((void**)&u,       d_u);
    cudaGetSymbolAddress((void**)&attn_WT, d_attn_WT);
    cudaGetSymbolAddress((void**)&Afh,     d_Afh);
    cudaGetSymbolAddress((void**)&Bvh,     d_Bvh);
    cudaGetSymbolAddress((void**)&h16h,    d_h16h);
    cudaGetSymbolAddress((void**)&h16l,    d_h16l);
    cudaGetSymbolAddress((void**)&bar,     d_bar);

    cudaFuncSetAttribute(vgemm512_kernel,
                         cudaFuncAttributeMaxDynamicSharedMemorySize, VG_SMEM);
    cudaFuncSetAttribute(gemm3h_kernel,
                         cudaFuncAttributeMaxDynamicSharedMemorySize, G3_SMEM);
    cudaFuncSetAttribute(gru_persist_kernel,
                         cudaFuncAttributeMaxDynamicSharedMemorySize, GP_SMEM);

    // (1) image -> class embedding mean  (also resets GRU barrier counters)
    topk_cls_kernel<<<B_, 256>>>(img_rep, class_emb, cls, bar);

    // (2) proj = cls @ proj_W^T + b   (fp16 3-term)
    gemm3h_kernel<<<dim3(D_ / 128, B_ / 128), 256, G3_SMEM>>>(
        cls, D_, proj_W, D_, proj_b, proj, D_, B_, D_, D_);

    // (3) batchnorm (train mode) in place
    bn_kernel<<<1, D_>>>(proj, bn_gamma, bn_beta);

    // (4) vocab_W -> fp16
    f2h_kernel<<<1184, 256>>>(vocab_W, Bvh, V_ * 2 * H_ / 4);

    // (5) build X (B*T, D)
    build_x_kernel<<<(B_ * T_ * D_) / 256, 256>>>(proj, emb_table, targets, X);

    // (6) GI = X @ Wih^T + bih  (fp16 3-term)
    gemm3h_kernel<<<dim3((3 * H_) / 128, (B_ * T_) / 128), 256, G3_SMEM>>>(
        X, D_, gru_Wih, D_, gru_bih, GI, 3 * H_, B_ * T_, 3 * H_, D_);

    // (7) transpose attn_W
    transpose_kernel<<<(H_ * H_) / 256, 256>>>(attn_W, attn_WT);

    // (8) persistent GRU (H loads double-buffered; writes f32 feats + fp16 Afh)
    gru_persist_kernel<<<64, 256, GP_SMEM>>>(
        gru_Whh, gru_bhh, GI, real_lens, feats, Afh, h0, h1, h16h, h16l, bar);

    // (9) u = out @ attn_W  (fp16 3-term via transposed weights)
    gemm3h_kernel<<<dim3(H_ / 128, (B_ * T_) / 128), 256, G3_SMEM>>>(
        feats, 2 * H_, attn_WT, H_, nullptr, u, H_, B_ * T_, H_, H_);

    // (10) causal attention -> ct written as fp16 directly into Afh right half
    attn_kernel<<<B_, 256>>>(feats, u, Afh);

    // (11) logits = Afh @ Bvh^T + vocab_b  (fp16, 512-thread, .cs epilogue)
    vgemm512_kernel<<<dim3((B_ * T_) / 128, V_ / 128), 512, VG_SMEM>>>(
        Afh, Bvh, vocab_b, out, 2 * H_, V_);
}